// round 5
// baseline (speedup 1.0000x reference)
#include <cuda_runtime.h>
#include <cuda_bf16.h>

// ---------------------------------------------------------------------------
// 2-layer GCN: h = relu(GCN(relu(GCN(x, W1, b1)), W2, b2))
// GCNConv: out = D^{-1/2}(A+I)D^{-1/2} X W + b      (edge_index is int32)
//
// R5: gather unrolled x4 (4 independent accumulators -> MLP=4 per lane).
// ---------------------------------------------------------------------------

#define MAX_N 50000
#define MAX_E 600000
#define H 128
#define SCAN_T 1024

__device__ float g_dinv[MAX_N];
__device__ int   g_cnt[MAX_N];
__device__ int   g_off[MAX_N + 1];
__device__ int   g_cursor[MAX_N];
__device__ int   g_csr_src[MAX_E];
__device__ float g_xw[MAX_N * H];
__device__ float g_h[MAX_N * H];

// ---------------------------------------------------------------------------
// CSR build
// ---------------------------------------------------------------------------
__global__ void zero_cnt_kernel(int* cnt, int n) {
    int i = blockIdx.x * blockDim.x + threadIdx.x;
    if (i < n) cnt[i] = 0;
}

__global__ void count_kernel(const int* __restrict__ ei, int* cnt, int e) {
    int i = blockIdx.x * blockDim.x + threadIdx.x;
    if (i < e) atomicAdd(&cnt[ei[e + i]], 1);
}

// Single-block exclusive scan over n counts -> off, cursor; dinv = rsqrt(1+cnt).
__global__ void __launch_bounds__(SCAN_T) scan_kernel(
    const int* __restrict__ cnt, int* __restrict__ off,
    int* __restrict__ cursor, float* __restrict__ dinv, int n)
{
    __shared__ int part[SCAN_T];
    const int t = threadIdx.x;
    const int chunk = (n + SCAN_T - 1) / SCAN_T;
    const int beg = t * chunk;
    const int end = min(beg + chunk, n);

    int local = 0;
    for (int i = beg; i < end; i++) local += cnt[i];
    part[t] = local;
    __syncthreads();

    for (int s = 1; s < SCAN_T; s <<= 1) {
        int v = (t >= s) ? part[t - s] : 0;
        __syncthreads();
        part[t] += v;
        __syncthreads();
    }

    int run = (t == 0) ? 0 : part[t - 1];
    for (int i = beg; i < end; i++) {
        int c = cnt[i];
        off[i] = run;
        cursor[i] = run;
        dinv[i] = rsqrtf(1.0f + (float)c);
        run += c;
    }
    if (t == SCAN_T - 1) off[n] = run;
}

__global__ void fill_kernel(const int* __restrict__ ei,
                            int* __restrict__ cursor,
                            int* __restrict__ csr_src, int e)
{
    int i = blockIdx.x * blockDim.x + threadIdx.x;
    if (i < e) {
        int s = ei[i];
        int d = ei[e + i];
        int p = atomicAdd(&cursor[d], 1);
        csr_src[p] = s;
    }
}

// ---------------------------------------------------------------------------
// GEMM: xw = A @ W. Block 64 rows x 128 cols, thread tile 8x4.
// (fp32 scalar FFMA roofline-bound at ~48us; tensor-core rewrite is the
//  next-step optimization.)
// ---------------------------------------------------------------------------
__global__ void __launch_bounds__(256, 3) gemm128_kernel(
    const float* __restrict__ A, const float* __restrict__ W,
    float* __restrict__ xw, int n)
{
    __shared__ float xs[64][H];
    __shared__ float ws[32][H];

    const int tid = threadIdx.x;
    const int row0 = blockIdx.x * 64;

    const float4* A4 = reinterpret_cast<const float4*>(A);
#pragma unroll
    for (int i = tid; i < 64 * 32; i += 256) {
        int r = i >> 5, c4 = i & 31;
        int row = row0 + r;
        float4 v = make_float4(0.f, 0.f, 0.f, 0.f);
        if (row < n) v = A4[row * 32 + c4];
        reinterpret_cast<float4*>(&xs[r][0])[c4] = v;
    }

    const int tx = tid & 31;
    const int ty = tid >> 5;

    float acc[8][4];
#pragma unroll
    for (int r = 0; r < 8; r++)
#pragma unroll
        for (int c = 0; c < 4; c++) acc[r][c] = 0.f;

    const float4* W4 = reinterpret_cast<const float4*>(W);

#pragma unroll 1
    for (int kc = 0; kc < 4; kc++) {
        __syncthreads();
#pragma unroll
        for (int i = tid; i < 32 * 32; i += 256) {
            int r = i >> 5, c4 = i & 31;
            reinterpret_cast<float4*>(&ws[r][0])[c4] = W4[(kc * 32 + r) * 32 + c4];
        }
        __syncthreads();

#pragma unroll
        for (int k = 0; k < 32; k++) {
            float4 w4 = reinterpret_cast<float4*>(&ws[k][0])[tx];
            float a[8];
#pragma unroll
            for (int r = 0; r < 8; r++) a[r] = xs[ty * 8 + r][kc * 32 + k];
#pragma unroll
            for (int r = 0; r < 8; r++) {
                acc[r][0] += a[r] * w4.x;
                acc[r][1] += a[r] * w4.y;
                acc[r][2] += a[r] * w4.z;
                acc[r][3] += a[r] * w4.w;
            }
        }
    }

#pragma unroll
    for (int r = 0; r < 8; r++) {
        int row = row0 + ty * 8 + r;
        if (row < n) {
            float4 v = make_float4(acc[r][0], acc[r][1], acc[r][2], acc[r][3]);
            reinterpret_cast<float4*>(xw + (size_t)row * H)[tx] = v;
        }
    }
}

// ---------------------------------------------------------------------------
// Pull aggregation: one warp per node, unrolled x4 for MLP.
//   out[d] = relu( dinv[d]*( sum_s dinv[s]*xw[s] + dinv[d]*xw[d] ) + b )
// ---------------------------------------------------------------------------
__global__ void __launch_bounds__(256) gather_kernel(
    const int* __restrict__ csr_src,
    const int* __restrict__ off,
    const float* __restrict__ dinv,
    const float* __restrict__ xw,
    const float* __restrict__ b,
    float* __restrict__ out, int n)
{
    int node = (blockIdx.x * blockDim.x + threadIdx.x) >> 5;
    int lane = threadIdx.x & 31;
    if (node >= n) return;

    const float4* xw4 = reinterpret_cast<const float4*>(xw);
    int j   = off[node];
    const int end = off[node + 1];

    float4 acc0 = make_float4(0.f, 0.f, 0.f, 0.f);
    float4 acc1 = make_float4(0.f, 0.f, 0.f, 0.f);
    float4 acc2 = make_float4(0.f, 0.f, 0.f, 0.f);
    float4 acc3 = make_float4(0.f, 0.f, 0.f, 0.f);

    // Main loop: 4 independent gathers in flight per lane.
    for (; j + 3 < end; j += 4) {
        int s0 = csr_src[j];
        int s1 = csr_src[j + 1];
        int s2 = csr_src[j + 2];
        int s3 = csr_src[j + 3];
        float d0 = dinv[s0];
        float d1 = dinv[s1];
        float d2 = dinv[s2];
        float d3 = dinv[s3];
        float4 v0 = xw4[(size_t)s0 * 32 + lane];
        float4 v1 = xw4[(size_t)s1 * 32 + lane];
        float4 v2 = xw4[(size_t)s2 * 32 + lane];
        float4 v3 = xw4[(size_t)s3 * 32 + lane];
        acc0.x += d0 * v0.x; acc0.y += d0 * v0.y; acc0.z += d0 * v0.z; acc0.w += d0 * v0.w;
        acc1.x += d1 * v1.x; acc1.y += d1 * v1.y; acc1.z += d1 * v1.z; acc1.w += d1 * v1.w;
        acc2.x += d2 * v2.x; acc2.y += d2 * v2.y; acc2.z += d2 * v2.z; acc2.w += d2 * v2.w;
        acc3.x += d3 * v3.x; acc3.y += d3 * v3.y; acc3.z += d3 * v3.z; acc3.w += d3 * v3.w;
    }
    for (; j < end; j++) {
        int s0 = csr_src[j];
        float d0 = dinv[s0];
        float4 v0 = xw4[(size_t)s0 * 32 + lane];
        acc0.x += d0 * v0.x; acc0.y += d0 * v0.y; acc0.z += d0 * v0.z; acc0.w += d0 * v0.w;
    }

    float dd = dinv[node];
    float4 xv = xw4[(size_t)node * 32 + lane];
    float4 bb = reinterpret_cast<const float4*>(b)[lane];

    float sx = acc0.x + acc1.x + acc2.x + acc3.x;
    float sy = acc0.y + acc1.y + acc2.y + acc3.y;
    float sz = acc0.z + acc1.z + acc2.z + acc3.z;
    float sw = acc0.w + acc1.w + acc2.w + acc3.w;

    float4 r;
    r.x = fmaxf(dd * (sx + dd * xv.x) + bb.x, 0.f);
    r.y = fmaxf(dd * (sy + dd * xv.y) + bb.y, 0.f);
    r.z = fmaxf(dd * (sz + dd * xv.z) + bb.z, 0.f);
    r.w = fmaxf(dd * (sw + dd * xv.w) + bb.w, 0.f);
    reinterpret_cast<float4*>(out)[(size_t)node * 32 + lane] = r;
}

// ---------------------------------------------------------------------------
// Launch
// ---------------------------------------------------------------------------
extern "C" void kernel_launch(void* const* d_in, const int* in_sizes, int n_in,
                              void* d_out, int out_size)
{
    const float* x  = (const float*)d_in[0];
    const int*   ei = (const int*)d_in[1];
    const float* W1 = (const float*)d_in[2];
    const float* b1 = (const float*)d_in[3];
    const float* W2 = (const float*)d_in[4];
    const float* b2 = (const float*)d_in[5];
    float* out = (float*)d_out;

    const int n = in_sizes[0] / H;       // 50000
    const int e = in_sizes[1] / 2;       // 600000

    float* dinv;   cudaGetSymbolAddress((void**)&dinv,   g_dinv);
    int*   cnt;    cudaGetSymbolAddress((void**)&cnt,    g_cnt);
    int*   off;    cudaGetSymbolAddress((void**)&off,    g_off);
    int*   cursor; cudaGetSymbolAddress((void**)&cursor, g_cursor);
    int*   csr;    cudaGetSymbolAddress((void**)&csr,    g_csr_src);
    float* xw;     cudaGetSymbolAddress((void**)&xw,     g_xw);
    float* h;      cudaGetSymbolAddress((void**)&h,      g_h);

    const int T = 256;
    const int blocks_n    = (n + T - 1) / T;
    const int blocks_e    = (e + T - 1) / T;
    const int blocks_gemm = (n + 63) / 64;
    const int blocks_gath = (n * 32 + T - 1) / T;

    // CSR build (shared by both layers)
    zero_cnt_kernel<<<blocks_n, T>>>(cnt, n);
    count_kernel<<<blocks_e, T>>>(ei, cnt, e);
    scan_kernel<<<1, SCAN_T>>>(cnt, off, cursor, dinv, n);
    fill_kernel<<<blocks_e, T>>>(ei, cursor, csr, e);

    // layer 1
    gemm128_kernel<<<blocks_gemm, T>>>(x, W1, xw, n);
    gather_kernel<<<blocks_gath, T>>>(csr, off, dinv, xw, b1, h, n);

    // layer 2
    gemm128_kernel<<<blocks_gemm, T>>>(h, W2, xw, n);
    gather_kernel<<<blocks_gath, T>>>(csr, off, dinv, xw, b2, out, n);
}

// round 6
// speedup vs baseline: 1.0856x; 1.0856x over previous
#include <cuda_runtime.h>
#include <cuda_bf16.h>
#include <cstdint>

// ---------------------------------------------------------------------------
// 2-layer GCN: h = relu(GCN(relu(GCN(x, W1, b1)), W2, b2))
// GCNConv: out = D^{-1/2}(A+I)D^{-1/2} X W + b      (edge_index is int32)
//
// R6: tf32 tensor-core GEMM (mma.sync.m16n8k8); CSR pull gather (x2 unroll)
//     with fused self-loop + bias + relu epilogue.
// ---------------------------------------------------------------------------

#define MAX_N 50000
#define MAX_E 600000
#define H 128
#define SCAN_T 1024

__device__ float g_dinv[MAX_N];
__device__ int   g_cnt[MAX_N];
__device__ int   g_off[MAX_N + 1];
__device__ int   g_cursor[MAX_N];
__device__ int   g_csr_src[MAX_E];
__device__ float g_xw[MAX_N * H];
__device__ float g_h[MAX_N * H];

// ---------------------------------------------------------------------------
// CSR build
// ---------------------------------------------------------------------------
__global__ void zero_cnt_kernel(int* cnt, int n) {
    int i = blockIdx.x * blockDim.x + threadIdx.x;
    if (i < n) cnt[i] = 0;
}

__global__ void count_kernel(const int* __restrict__ ei, int* cnt, int e) {
    int i = blockIdx.x * blockDim.x + threadIdx.x;
    if (i < e) atomicAdd(&cnt[ei[e + i]], 1);
}

__global__ void __launch_bounds__(SCAN_T) scan_kernel(
    const int* __restrict__ cnt, int* __restrict__ off,
    int* __restrict__ cursor, float* __restrict__ dinv, int n)
{
    __shared__ int part[SCAN_T];
    const int t = threadIdx.x;
    const int chunk = (n + SCAN_T - 1) / SCAN_T;
    const int beg = t * chunk;
    const int end = min(beg + chunk, n);

    int local = 0;
    for (int i = beg; i < end; i++) local += cnt[i];
    part[t] = local;
    __syncthreads();

    for (int s = 1; s < SCAN_T; s <<= 1) {
        int v = (t >= s) ? part[t - s] : 0;
        __syncthreads();
        part[t] += v;
        __syncthreads();
    }

    int run = (t == 0) ? 0 : part[t - 1];
    for (int i = beg; i < end; i++) {
        int c = cnt[i];
        off[i] = run;
        cursor[i] = run;
        dinv[i] = rsqrtf(1.0f + (float)c);
        run += c;
    }
    if (t == SCAN_T - 1) off[n] = run;
}

__global__ void fill_kernel(const int* __restrict__ ei,
                            int* __restrict__ cursor,
                            int* __restrict__ csr_src, int e)
{
    int i = blockIdx.x * blockDim.x + threadIdx.x;
    if (i < e) {
        int s = ei[i];
        int d = ei[e + i];
        int p = atomicAdd(&cursor[d], 1);
        csr_src[p] = s;
    }
}

// ---------------------------------------------------------------------------
// tf32 helpers
// ---------------------------------------------------------------------------
__device__ __forceinline__ uint32_t f2tf32(float f) {
    uint32_t r;
    asm("cvt.rna.tf32.f32 %0, %1;" : "=r"(r) : "f"(f));
    return r;
}

__device__ __forceinline__ void mma_tf32(float* c,
    uint32_t a0, uint32_t a1, uint32_t a2, uint32_t a3,
    uint32_t b0, uint32_t b1)
{
    asm volatile(
        "mma.sync.aligned.m16n8k8.row.col.f32.tf32.tf32.f32 "
        "{%0,%1,%2,%3}, {%4,%5,%6,%7}, {%8,%9}, {%0,%1,%2,%3};"
        : "+f"(c[0]), "+f"(c[1]), "+f"(c[2]), "+f"(c[3])
        : "r"(a0), "r"(a1), "r"(a2), "r"(a3), "r"(b0), "r"(b1));
}

// ---------------------------------------------------------------------------
// GEMM (tensor cores): xw = A @ W.
// Block 128 thr (4 warps) -> 64 rows x 128 cols; warp -> 16 rows x 128 cols.
// W staged in smem per 16-row K-chunk, tf32-converted, row stride 136
// (bank = 8*(l&3)+(l>>2), conflict-free). A frags direct from global (L1).
// ---------------------------------------------------------------------------
#define WPAD 136

__global__ void __launch_bounds__(128) gemm_tf32_kernel(
    const float* __restrict__ A, const float* __restrict__ W,
    float* __restrict__ xw, int n)
{
    __shared__ float Ws[16][WPAD];

    const int tid  = threadIdx.x;
    const int lane = tid & 31;
    const int warp = tid >> 5;
    const int g    = lane >> 2;   // group id (0..7)
    const int t4   = lane & 3;    // thread-in-group (0..3)
    const int m0   = blockIdx.x * 64 + warp * 16;

    float acc[16][4];
#pragma unroll
    for (int nt = 0; nt < 16; nt++)
#pragma unroll
        for (int c = 0; c < 4; c++) acc[nt][c] = 0.f;

    const float4* W4 = reinterpret_cast<const float4*>(W);
    const int r0 = m0 + g;
    const int r1 = r0 + 8;
    const bool v0 = r0 < n;
    const bool v1 = r1 < n;

#pragma unroll 1
    for (int kc = 0; kc < 8; kc++) {
        __syncthreads();
        // Load W rows [kc*16, kc*16+16), convert to tf32 in smem.
#pragma unroll
        for (int i = tid; i < 16 * 32; i += 128) {
            int r = i >> 5, c4 = i & 31;
            float4 v = W4[(kc * 16 + r) * 32 + c4];
            Ws[r][c4 * 4 + 0] = __uint_as_float(f2tf32(v.x));
            Ws[r][c4 * 4 + 1] = __uint_as_float(f2tf32(v.y));
            Ws[r][c4 * 4 + 2] = __uint_as_float(f2tf32(v.z));
            Ws[r][c4 * 4 + 3] = __uint_as_float(f2tf32(v.w));
        }
        __syncthreads();

#pragma unroll
        for (int kk = 0; kk < 2; kk++) {
            const int k0 = kc * 16 + kk * 8;
            const int c0 = k0 + t4;
            uint32_t a0 = v0 ? f2tf32(A[(size_t)r0 * H + c0])     : 0u;
            uint32_t a1 = v1 ? f2tf32(A[(size_t)r1 * H + c0])     : 0u;
            uint32_t a2 = v0 ? f2tf32(A[(size_t)r0 * H + c0 + 4]) : 0u;
            uint32_t a3 = v1 ? f2tf32(A[(size_t)r1 * H + c0 + 4]) : 0u;

#pragma unroll
            for (int nt = 0; nt < 16; nt++) {
                uint32_t b0 = __float_as_uint(Ws[kk * 8 + t4    ][nt * 8 + g]);
                uint32_t b1 = __float_as_uint(Ws[kk * 8 + t4 + 4][nt * 8 + g]);
                mma_tf32(acc[nt], a0, a1, a2, a3, b0, b1);
            }
        }
    }

    // Epilogue: write C. Lane holds rows {r0, r1}, cols {2*t4, 2*t4+1} + 8*nt.
#pragma unroll
    for (int nt = 0; nt < 16; nt++) {
        int col = nt * 8 + 2 * t4;
        if (v0) {
            float2 u = make_float2(acc[nt][0], acc[nt][1]);
            *reinterpret_cast<float2*>(xw + (size_t)r0 * H + col) = u;
        }
        if (v1) {
            float2 u = make_float2(acc[nt][2], acc[nt][3]);
            *reinterpret_cast<float2*>(xw + (size_t)r1 * H + col) = u;
        }
    }
}

// ---------------------------------------------------------------------------
// Pull aggregation: one warp per node (x2 unroll).
//   out[d] = relu( dinv[d]*( sum_s dinv[s]*xw[s] + dinv[d]*xw[d] ) + b )
// ---------------------------------------------------------------------------
__global__ void __launch_bounds__(256) gather_kernel(
    const int* __restrict__ csr_src,
    const int* __restrict__ off,
    const float* __restrict__ dinv,
    const float* __restrict__ xw,
    const float* __restrict__ b,
    float* __restrict__ out, int n)
{
    int node = (blockIdx.x * blockDim.x + threadIdx.x) >> 5;
    int lane = threadIdx.x & 31;
    if (node >= n) return;

    const float4* xw4 = reinterpret_cast<const float4*>(xw);
    int j   = off[node];
    const int end = off[node + 1];

    float4 acc0 = make_float4(0.f, 0.f, 0.f, 0.f);
    float4 acc1 = make_float4(0.f, 0.f, 0.f, 0.f);

    for (; j + 1 < end; j += 2) {
        int s0 = csr_src[j];
        int s1 = csr_src[j + 1];
        float d0 = dinv[s0];
        float d1 = dinv[s1];
        float4 u0 = xw4[(size_t)s0 * 32 + lane];
        float4 u1 = xw4[(size_t)s1 * 32 + lane];
        acc0.x += d0 * u0.x; acc0.y += d0 * u0.y;
        acc0.z += d0 * u0.z; acc0.w += d0 * u0.w;
        acc1.x += d1 * u1.x; acc1.y += d1 * u1.y;
        acc1.z += d1 * u1.z; acc1.w += d1 * u1.w;
    }
    if (j < end) {
        int s0 = csr_src[j];
        float d0 = dinv[s0];
        float4 u0 = xw4[(size_t)s0 * 32 + lane];
        acc0.x += d0 * u0.x; acc0.y += d0 * u0.y;
        acc0.z += d0 * u0.z; acc0.w += d0 * u0.w;
    }

    float dd = dinv[node];
    float4 xv = xw4[(size_t)node * 32 + lane];
    float4 bb = reinterpret_cast<const float4*>(b)[lane];

    float4 r;
    r.x = fmaxf(dd * (acc0.x + acc1.x + dd * xv.x) + bb.x, 0.f);
    r.y = fmaxf(dd * (acc0.y + acc1.y + dd * xv.y) + bb.y, 0.f);
    r.z = fmaxf(dd * (acc0.z + acc1.z + dd * xv.z) + bb.z, 0.f);
    r.w = fmaxf(dd * (acc0.w + acc1.w + dd * xv.w) + bb.w, 0.f);
    reinterpret_cast<float4*>(out)[(size_t)node * 32 + lane] = r;
}

// ---------------------------------------------------------------------------
// Launch
// ---------------------------------------------------------------------------
extern "C" void kernel_launch(void* const* d_in, const int* in_sizes, int n_in,
                              void* d_out, int out_size)
{
    const float* x  = (const float*)d_in[0];
    const int*   ei = (const int*)d_in[1];
    const float* W1 = (const float*)d_in[2];
    const float* b1 = (const float*)d_in[3];
    const float* W2 = (const float*)d_in[4];
    const float* b2 = (const float*)d_in[5];
    float* out = (float*)d_out;

    const int n = in_sizes[0] / H;       // 50000
    const int e = in_sizes[1] / 2;       // 600000

    float* dinv;   cudaGetSymbolAddress((void**)&dinv,   g_dinv);
    int*   cnt;    cudaGetSymbolAddress((void**)&cnt,    g_cnt);
    int*   off;    cudaGetSymbolAddress((void**)&off,    g_off);
    int*   cursor; cudaGetSymbolAddress((void**)&cursor, g_cursor);
    int*   csr;    cudaGetSymbolAddress((void**)&csr,    g_csr_src);
    float* xw;     cudaGetSymbolAddress((void**)&xw,     g_xw);
    float* h;      cudaGetSymbolAddress((void**)&h,      g_h);

    const int T = 256;
    const int blocks_n    = (n + T - 1) / T;
    const int blocks_e    = (e + T - 1) / T;
    const int blocks_gemm = (n + 63) / 64;
    const int blocks_gath = (n * 32 + T - 1) / T;

    // CSR build (shared by both layers)
    zero_cnt_kernel<<<blocks_n, T>>>(cnt, n);
    count_kernel<<<blocks_e, T>>>(ei, cnt, e);
    scan_kernel<<<1, SCAN_T>>>(cnt, off, cursor, dinv, n);
    fill_kernel<<<blocks_e, T>>>(ei, cursor, csr, e);

    // layer 1
    gemm_tf32_kernel<<<blocks_gemm, 128>>>(x, W1, xw, n);
    gather_kernel<<<blocks_gath, T>>>(csr, off, dinv, xw, b1, h, n);

    // layer 2
    gemm_tf32_kernel<<<blocks_gemm, 128>>>(h, W2, xw, n);
    gather_kernel<<<blocks_gath, T>>>(csr, off, dinv, xw, b2, out, n);
}

// round 7
// speedup vs baseline: 1.2301x; 1.1331x over previous
#include <cuda_runtime.h>
#include <cuda_bf16.h>
#include <cstdint>

// ---------------------------------------------------------------------------
// 2-layer GCN: h = relu(GCN(relu(GCN(x, W1, b1)), W2, b2))
// GCNConv: out = D^{-1/2}(A+I)D^{-1/2} X W + b      (edge_index is int32)
//
// R7: pipelined tf32 GEMM — W staged once per CTA (dynamic smem, 1 sync),
//     256 thr / 128 rows, A-fragment prefetch double buffer.
//     Gather / CSR unchanged from R6 (best).
// ---------------------------------------------------------------------------

#define MAX_N 50000
#define MAX_E 600000
#define H 128
#define SCAN_T 1024
#define WPAD 136

__device__ float g_dinv[MAX_N];
__device__ int   g_cnt[MAX_N];
__device__ int   g_off[MAX_N + 1];
__device__ int   g_cursor[MAX_N];
__device__ int   g_csr_src[MAX_E];
__device__ float g_xw[MAX_N * H];
__device__ float g_h[MAX_N * H];

// ---------------------------------------------------------------------------
// CSR build
// ---------------------------------------------------------------------------
__global__ void zero_cnt_kernel(int* cnt, int n) {
    int i = blockIdx.x * blockDim.x + threadIdx.x;
    if (i < n) cnt[i] = 0;
}

__global__ void count_kernel(const int* __restrict__ ei, int* cnt, int e) {
    int i = blockIdx.x * blockDim.x + threadIdx.x;
    if (i < e) atomicAdd(&cnt[ei[e + i]], 1);
}

__global__ void __launch_bounds__(SCAN_T) scan_kernel(
    const int* __restrict__ cnt, int* __restrict__ off,
    int* __restrict__ cursor, float* __restrict__ dinv, int n)
{
    __shared__ int part[SCAN_T];
    const int t = threadIdx.x;
    const int chunk = (n + SCAN_T - 1) / SCAN_T;
    const int beg = t * chunk;
    const int end = min(beg + chunk, n);

    int local = 0;
    for (int i = beg; i < end; i++) local += cnt[i];
    part[t] = local;
    __syncthreads();

    for (int s = 1; s < SCAN_T; s <<= 1) {
        int v = (t >= s) ? part[t - s] : 0;
        __syncthreads();
        part[t] += v;
        __syncthreads();
    }

    int run = (t == 0) ? 0 : part[t - 1];
    for (int i = beg; i < end; i++) {
        int c = cnt[i];
        off[i] = run;
        cursor[i] = run;
        dinv[i] = rsqrtf(1.0f + (float)c);
        run += c;
    }
    if (t == SCAN_T - 1) off[n] = run;
}

__global__ void fill_kernel(const int* __restrict__ ei,
                            int* __restrict__ cursor,
                            int* __restrict__ csr_src, int e)
{
    int i = blockIdx.x * blockDim.x + threadIdx.x;
    if (i < e) {
        int s = ei[i];
        int d = ei[e + i];
        int p = atomicAdd(&cursor[d], 1);
        csr_src[p] = s;
    }
}

// ---------------------------------------------------------------------------
// tf32 helpers
// ---------------------------------------------------------------------------
__device__ __forceinline__ uint32_t f2tf32(float f) {
    uint32_t r;
    asm("cvt.rna.tf32.f32 %0, %1;" : "=r"(r) : "f"(f));
    return r;
}

__device__ __forceinline__ void mma_tf32(float* c,
    uint32_t a0, uint32_t a1, uint32_t a2, uint32_t a3,
    uint32_t b0, uint32_t b1)
{
    asm volatile(
        "mma.sync.aligned.m16n8k8.row.col.f32.tf32.tf32.f32 "
        "{%0,%1,%2,%3}, {%4,%5,%6,%7}, {%8,%9}, {%0,%1,%2,%3};"
        : "+f"(c[0]), "+f"(c[1]), "+f"(c[2]), "+f"(c[3])
        : "r"(a0), "r"(a1), "r"(a2), "r"(a3), "r"(b0), "r"(b1));
}

// ---------------------------------------------------------------------------
// GEMM (tensor cores, pipelined): xw = A @ W.
// Block 256 thr (8 warps) -> 128 rows; warp -> 16 rows x 128 cols.
// Full W (tf32) staged once in dynamic smem [128][136]; single __syncthreads.
// A fragments double-buffered in registers (prefetch chunk kc+1 during kc).
// ---------------------------------------------------------------------------
__global__ void __launch_bounds__(256) gemm_tf32_kernel(
    const float* __restrict__ A, const float* __restrict__ W,
    float* __restrict__ xw, int n)
{
    extern __shared__ float Ws[];   // [128][WPAD]

    const int tid  = threadIdx.x;
    const int lane = tid & 31;
    const int warp = tid >> 5;
    const int g    = lane >> 2;   // 0..7
    const int t4   = lane & 3;    // 0..3
    const int m0   = blockIdx.x * 128 + warp * 16;

    // Stage all of W as tf32: 128 rows x 32 float4, 16 float4 per thread.
    const float4* W4 = reinterpret_cast<const float4*>(W);
#pragma unroll
    for (int i = tid; i < 128 * 32; i += 256) {
        int r = i >> 5, c4 = i & 31;
        float4 v = W4[r * 32 + c4];
        float* dstp = &Ws[r * WPAD + c4 * 4];
        dstp[0] = __uint_as_float(f2tf32(v.x));
        dstp[1] = __uint_as_float(f2tf32(v.y));
        dstp[2] = __uint_as_float(f2tf32(v.z));
        dstp[3] = __uint_as_float(f2tf32(v.w));
    }

    float acc[16][4];
#pragma unroll
    for (int nt = 0; nt < 16; nt++)
#pragma unroll
        for (int c = 0; c < 4; c++) acc[nt][c] = 0.f;

    const int r0 = m0 + g;
    const int r1 = r0 + 8;
    const bool v0 = r0 < n;
    const bool v1 = r1 < n;
    const float* Ar0 = A + (size_t)r0 * H;
    const float* Ar1 = A + (size_t)r1 * H;

    __syncthreads();

    // Prologue: fragments for chunk 0.
    uint32_t a0 = v0 ? f2tf32(Ar0[t4])     : 0u;
    uint32_t a1 = v1 ? f2tf32(Ar1[t4])     : 0u;
    uint32_t a2 = v0 ? f2tf32(Ar0[t4 + 4]) : 0u;
    uint32_t a3 = v1 ? f2tf32(Ar1[t4 + 4]) : 0u;

#pragma unroll
    for (int kc = 0; kc < 16; kc++) {
        uint32_t na0 = 0u, na1 = 0u, na2 = 0u, na3 = 0u;
        if (kc < 15) {
            const int c0 = (kc + 1) * 8 + t4;
            na0 = v0 ? f2tf32(Ar0[c0])     : 0u;
            na1 = v1 ? f2tf32(Ar1[c0])     : 0u;
            na2 = v0 ? f2tf32(Ar0[c0 + 4]) : 0u;
            na3 = v1 ? f2tf32(Ar1[c0 + 4]) : 0u;
        }

        const float* wb0 = &Ws[(kc * 8 + t4) * WPAD];
        const float* wb1 = &Ws[(kc * 8 + t4 + 4) * WPAD];
#pragma unroll
        for (int nt = 0; nt < 16; nt++) {
            uint32_t b0 = __float_as_uint(wb0[nt * 8 + g]);
            uint32_t b1 = __float_as_uint(wb1[nt * 8 + g]);
            mma_tf32(acc[nt], a0, a1, a2, a3, b0, b1);
        }

        a0 = na0; a1 = na1; a2 = na2; a3 = na3;
    }

    // Epilogue: lane holds rows {r0,r1}, cols {2*t4, 2*t4+1} + 8*nt.
#pragma unroll
    for (int nt = 0; nt < 16; nt++) {
        int col = nt * 8 + 2 * t4;
        if (v0) {
            float2 u = make_float2(acc[nt][0], acc[nt][1]);
            *reinterpret_cast<float2*>(xw + (size_t)r0 * H + col) = u;
        }
        if (v1) {
            float2 u = make_float2(acc[nt][2], acc[nt][3]);
            *reinterpret_cast<float2*>(xw + (size_t)r1 * H + col) = u;
        }
    }
}

// ---------------------------------------------------------------------------
// Pull aggregation: one warp per node (x2 unroll).
//   out[d] = relu( dinv[d]*( sum_s dinv[s]*xw[s] + dinv[d]*xw[d] ) + b )
// ---------------------------------------------------------------------------
__global__ void __launch_bounds__(256) gather_kernel(
    const int* __restrict__ csr_src,
    const int* __restrict__ off,
    const float* __restrict__ dinv,
    const float* __restrict__ xw,
    const float* __restrict__ b,
    float* __restrict__ out, int n)
{
    int node = (blockIdx.x * blockDim.x + threadIdx.x) >> 5;
    int lane = threadIdx.x & 31;
    if (node >= n) return;

    const float4* xw4 = reinterpret_cast<const float4*>(xw);
    int j   = off[node];
    const int end = off[node + 1];

    float4 acc0 = make_float4(0.f, 0.f, 0.f, 0.f);
    float4 acc1 = make_float4(0.f, 0.f, 0.f, 0.f);

    for (; j + 1 < end; j += 2) {
        int s0 = csr_src[j];
        int s1 = csr_src[j + 1];
        float d0 = dinv[s0];
        float d1 = dinv[s1];
        float4 u0 = xw4[(size_t)s0 * 32 + lane];
        float4 u1 = xw4[(size_t)s1 * 32 + lane];
        acc0.x += d0 * u0.x; acc0.y += d0 * u0.y;
        acc0.z += d0 * u0.z; acc0.w += d0 * u0.w;
        acc1.x += d1 * u1.x; acc1.y += d1 * u1.y;
        acc1.z += d1 * u1.z; acc1.w += d1 * u1.w;
    }
    if (j < end) {
        int s0 = csr_src[j];
        float d0 = dinv[s0];
        float4 u0 = xw4[(size_t)s0 * 32 + lane];
        acc0.x += d0 * u0.x; acc0.y += d0 * u0.y;
        acc0.z += d0 * u0.z; acc0.w += d0 * u0.w;
    }

    float dd = dinv[node];
    float4 xv = xw4[(size_t)node * 32 + lane];
    float4 bb = reinterpret_cast<const float4*>(b)[lane];

    float4 r;
    r.x = fmaxf(dd * (acc0.x + acc1.x + dd * xv.x) + bb.x, 0.f);
    r.y = fmaxf(dd * (acc0.y + acc1.y + dd * xv.y) + bb.y, 0.f);
    r.z = fmaxf(dd * (acc0.z + acc1.z + dd * xv.z) + bb.z, 0.f);
    r.w = fmaxf(dd * (acc0.w + acc1.w + dd * xv.w) + bb.w, 0.f);
    reinterpret_cast<float4*>(out)[(size_t)node * 32 + lane] = r;
}

// ---------------------------------------------------------------------------
// Launch
// ---------------------------------------------------------------------------
extern "C" void kernel_launch(void* const* d_in, const int* in_sizes, int n_in,
                              void* d_out, int out_size)
{
    const float* x  = (const float*)d_in[0];
    const int*   ei = (const int*)d_in[1];
    const float* W1 = (const float*)d_in[2];
    const float* b1 = (const float*)d_in[3];
    const float* W2 = (const float*)d_in[4];
    const float* b2 = (const float*)d_in[5];
    float* out = (float*)d_out;

    const int n = in_sizes[0] / H;       // 50000
    const int e = in_sizes[1] / 2;       // 600000

    float* dinv;   cudaGetSymbolAddress((void**)&dinv,   g_dinv);
    int*   cnt;    cudaGetSymbolAddress((void**)&cnt,    g_cnt);
    int*   off;    cudaGetSymbolAddress((void**)&off,    g_off);
    int*   cursor; cudaGetSymbolAddress((void**)&cursor, g_cursor);
    int*   csr;    cudaGetSymbolAddress((void**)&csr,    g_csr_src);
    float* xw;     cudaGetSymbolAddress((void**)&xw,     g_xw);
    float* h;      cudaGetSymbolAddress((void**)&h,      g_h);

    const int smem_w = 128 * WPAD * sizeof(float);   // 69,632 B
    static int smem_set = 0;
    if (!smem_set) {
        cudaFuncSetAttribute(gemm_tf32_kernel,
                             cudaFuncAttributeMaxDynamicSharedMemorySize, smem_w);
        smem_set = 1;
    }

    const int T = 256;
    const int blocks_n    = (n + T - 1) / T;
    const int blocks_e    = (e + T - 1) / T;
    const int blocks_gemm = (n + 127) / 128;
    const int blocks_gath = (n * 32 + T - 1) / T;

    // CSR build (shared by both layers)
    zero_cnt_kernel<<<blocks_n, T>>>(cnt, n);
    count_kernel<<<blocks_e, T>>>(ei, cnt, e);
    scan_kernel<<<1, SCAN_T>>>(cnt, off, cursor, dinv, n);
    fill_kernel<<<blocks_e, T>>>(ei, cursor, csr, e);

    // layer 1
    gemm_tf32_kernel<<<blocks_gemm, T, smem_w>>>(x, W1, xw, n);
    gather_kernel<<<blocks_gath, T>>>(csr, off, dinv, xw, b1, h, n);

    // layer 2
    gemm_tf32_kernel<<<blocks_gemm, T, smem_w>>>(h, W2, xw, n);
    gather_kernel<<<blocks_gath, T>>>(csr, off, dinv, xw, b2, out, n);
}

// round 8
// speedup vs baseline: 1.2961x; 1.0536x over previous
#include <cuda_runtime.h>
#include <cuda_fp16.h>
#include <cstdint>

// ---------------------------------------------------------------------------
// 2-layer GCN: h = relu(GCN(relu(GCN(x, W1, b1)), W2, b2))
// GCNConv: out = D^{-1/2}(A+I)D^{-1/2} X W + b      (edge_index is int32)
//
// R8: xw stored as fp16 (halves gather traffic 307->153 MB/layer);
//     fp32 accumulation in gather; tf32 pipelined GEMM unchanged otherwise.
// ---------------------------------------------------------------------------

#define MAX_N 50000
#define MAX_E 600000
#define H 128
#define SCAN_T 1024
#define WPAD 136

__device__ float  g_dinv[MAX_N];
__device__ int    g_cnt[MAX_N];
__device__ int    g_off[MAX_N + 1];
__device__ int    g_cursor[MAX_N];
__device__ int    g_csr_src[MAX_E];
__device__ __half g_xw[MAX_N * H];
__device__ float  g_h[MAX_N * H];

// ---------------------------------------------------------------------------
// CSR build
// ---------------------------------------------------------------------------
__global__ void zero_cnt_kernel(int* cnt, int n) {
    int i = blockIdx.x * blockDim.x + threadIdx.x;
    if (i < n) cnt[i] = 0;
}

__global__ void count_kernel(const int* __restrict__ ei, int* cnt, int e) {
    int i = blockIdx.x * blockDim.x + threadIdx.x;
    if (i < e) atomicAdd(&cnt[ei[e + i]], 1);
}

__global__ void __launch_bounds__(SCAN_T) scan_kernel(
    const int* __restrict__ cnt, int* __restrict__ off,
    int* __restrict__ cursor, float* __restrict__ dinv, int n)
{
    __shared__ int part[SCAN_T];
    const int t = threadIdx.x;
    const int chunk = (n + SCAN_T - 1) / SCAN_T;
    const int beg = t * chunk;
    const int end = min(beg + chunk, n);

    int local = 0;
    for (int i = beg; i < end; i++) local += cnt[i];
    part[t] = local;
    __syncthreads();

    for (int s = 1; s < SCAN_T; s <<= 1) {
        int v = (t >= s) ? part[t - s] : 0;
        __syncthreads();
        part[t] += v;
        __syncthreads();
    }

    int run = (t == 0) ? 0 : part[t - 1];
    for (int i = beg; i < end; i++) {
        int c = cnt[i];
        off[i] = run;
        cursor[i] = run;
        dinv[i] = rsqrtf(1.0f + (float)c);
        run += c;
    }
    if (t == SCAN_T - 1) off[n] = run;
}

__global__ void fill_kernel(const int* __restrict__ ei,
                            int* __restrict__ cursor,
                            int* __restrict__ csr_src, int e)
{
    int i = blockIdx.x * blockDim.x + threadIdx.x;
    if (i < e) {
        int s = ei[i];
        int d = ei[e + i];
        int p = atomicAdd(&cursor[d], 1);
        csr_src[p] = s;
    }
}

// ---------------------------------------------------------------------------
// tf32 helpers
// ---------------------------------------------------------------------------
__device__ __forceinline__ uint32_t f2tf32(float f) {
    uint32_t r;
    asm("cvt.rna.tf32.f32 %0, %1;" : "=r"(r) : "f"(f));
    return r;
}

__device__ __forceinline__ void mma_tf32(float* c,
    uint32_t a0, uint32_t a1, uint32_t a2, uint32_t a3,
    uint32_t b0, uint32_t b1)
{
    asm volatile(
        "mma.sync.aligned.m16n8k8.row.col.f32.tf32.tf32.f32 "
        "{%0,%1,%2,%3}, {%4,%5,%6,%7}, {%8,%9}, {%0,%1,%2,%3};"
        : "+f"(c[0]), "+f"(c[1]), "+f"(c[2]), "+f"(c[3])
        : "r"(a0), "r"(a1), "r"(a2), "r"(a3), "r"(b0), "r"(b1));
}

// ---------------------------------------------------------------------------
// GEMM (tensor cores, pipelined): xw(fp16) = A(fp32) @ W(fp32 -> tf32).
// Block 256 thr (8 warps) -> 128 rows; warp -> 16 rows x 128 cols.
// Full W staged once in dynamic smem [128][136]; single __syncthreads.
// A fragments double-buffered in registers.
// ---------------------------------------------------------------------------
__global__ void __launch_bounds__(256) gemm_tf32_kernel(
    const float* __restrict__ A, const float* __restrict__ W,
    __half* __restrict__ xw, int n)
{
    extern __shared__ float Ws[];   // [128][WPAD]

    const int tid  = threadIdx.x;
    const int lane = tid & 31;
    const int warp = tid >> 5;
    const int g    = lane >> 2;   // 0..7
    const int t4   = lane & 3;    // 0..3
    const int m0   = blockIdx.x * 128 + warp * 16;

    const float4* W4 = reinterpret_cast<const float4*>(W);
#pragma unroll
    for (int i = tid; i < 128 * 32; i += 256) {
        int r = i >> 5, c4 = i & 31;
        float4 v = W4[r * 32 + c4];
        float* dstp = &Ws[r * WPAD + c4 * 4];
        dstp[0] = __uint_as_float(f2tf32(v.x));
        dstp[1] = __uint_as_float(f2tf32(v.y));
        dstp[2] = __uint_as_float(f2tf32(v.z));
        dstp[3] = __uint_as_float(f2tf32(v.w));
    }

    float acc[16][4];
#pragma unroll
    for (int nt = 0; nt < 16; nt++)
#pragma unroll
        for (int c = 0; c < 4; c++) acc[nt][c] = 0.f;

    const int r0 = m0 + g;
    const int r1 = r0 + 8;
    const bool v0 = r0 < n;
    const bool v1 = r1 < n;
    const float* Ar0 = A + (size_t)r0 * H;
    const float* Ar1 = A + (size_t)r1 * H;

    __syncthreads();

    uint32_t a0 = v0 ? f2tf32(Ar0[t4])     : 0u;
    uint32_t a1 = v1 ? f2tf32(Ar1[t4])     : 0u;
    uint32_t a2 = v0 ? f2tf32(Ar0[t4 + 4]) : 0u;
    uint32_t a3 = v1 ? f2tf32(Ar1[t4 + 4]) : 0u;

#pragma unroll
    for (int kc = 0; kc < 16; kc++) {
        uint32_t na0 = 0u, na1 = 0u, na2 = 0u, na3 = 0u;
        if (kc < 15) {
            const int c0 = (kc + 1) * 8 + t4;
            na0 = v0 ? f2tf32(Ar0[c0])     : 0u;
            na1 = v1 ? f2tf32(Ar1[c0])     : 0u;
            na2 = v0 ? f2tf32(Ar0[c0 + 4]) : 0u;
            na3 = v1 ? f2tf32(Ar1[c0 + 4]) : 0u;
        }

        const float* wb0 = &Ws[(kc * 8 + t4) * WPAD];
        const float* wb1 = &Ws[(kc * 8 + t4 + 4) * WPAD];
#pragma unroll
        for (int nt = 0; nt < 16; nt++) {
            uint32_t b0 = __float_as_uint(wb0[nt * 8 + g]);
            uint32_t b1 = __float_as_uint(wb1[nt * 8 + g]);
            mma_tf32(acc[nt], a0, a1, a2, a3, b0, b1);
        }

        a0 = na0; a1 = na1; a2 = na2; a3 = na3;
    }

    // Epilogue: convert to fp16. Lane holds rows {r0,r1}, cols {2*t4,2*t4+1}+8*nt.
#pragma unroll
    for (int nt = 0; nt < 16; nt++) {
        int col = nt * 8 + 2 * t4;
        if (v0) {
            __half2 u = __float22half2_rn(make_float2(acc[nt][0], acc[nt][1]));
            *reinterpret_cast<__half2*>(xw + (size_t)r0 * H + col) = u;
        }
        if (v1) {
            __half2 u = __float22half2_rn(make_float2(acc[nt][2], acc[nt][3]));
            *reinterpret_cast<__half2*>(xw + (size_t)r1 * H + col) = u;
        }
    }
}

// ---------------------------------------------------------------------------
// Pull aggregation: one warp per node (x2 unroll), fp16 payload, fp32 acc.
//   out[d] = relu( dinv[d]*( sum_s dinv[s]*xw[s] + dinv[d]*xw[d] ) + b )
// Lane owns 4 columns: cols 4*lane .. 4*lane+3 (one uint2 = 4 halves = 8B).
// 32 lanes x 8B = 256B per neighbor row, fully coalesced.
// ---------------------------------------------------------------------------
__global__ void __launch_bounds__(256) gather_kernel(
    const int* __restrict__ csr_src,
    const int* __restrict__ off,
    const float* __restrict__ dinv,
    const __half* __restrict__ xw,
    const float* __restrict__ b,
    float* __restrict__ out, int n)
{
    int node = (blockIdx.x * blockDim.x + threadIdx.x) >> 5;
    int lane = threadIdx.x & 31;
    if (node >= n) return;

    const uint2* xw2 = reinterpret_cast<const uint2*>(xw);  // 4 halves per elt
    int j   = off[node];
    const int end = off[node + 1];

    float4 acc0 = make_float4(0.f, 0.f, 0.f, 0.f);
    float4 acc1 = make_float4(0.f, 0.f, 0.f, 0.f);

    for (; j + 1 < end; j += 2) {
        int s0 = csr_src[j];
        int s1 = csr_src[j + 1];
        float d0 = dinv[s0];
        float d1 = dinv[s1];
        uint2 u0 = xw2[(size_t)s0 * 32 + lane];
        uint2 u1 = xw2[(size_t)s1 * 32 + lane];
        float2 p0 = __half22float2(*reinterpret_cast<__half2*>(&u0.x));
        float2 q0 = __half22float2(*reinterpret_cast<__half2*>(&u0.y));
        float2 p1 = __half22float2(*reinterpret_cast<__half2*>(&u1.x));
        float2 q1 = __half22float2(*reinterpret_cast<__half2*>(&u1.y));
        acc0.x += d0 * p0.x; acc0.y += d0 * p0.y;
        acc0.z += d0 * q0.x; acc0.w += d0 * q0.y;
        acc1.x += d1 * p1.x; acc1.y += d1 * p1.y;
        acc1.z += d1 * q1.x; acc1.w += d1 * q1.y;
    }
    if (j < end) {
        int s0 = csr_src[j];
        float d0 = dinv[s0];
        uint2 u0 = xw2[(size_t)s0 * 32 + lane];
        float2 p0 = __half22float2(*reinterpret_cast<__half2*>(&u0.x));
        float2 q0 = __half22float2(*reinterpret_cast<__half2*>(&u0.y));
        acc0.x += d0 * p0.x; acc0.y += d0 * p0.y;
        acc0.z += d0 * q0.x; acc0.w += d0 * q0.y;
    }

    float dd = dinv[node];
    uint2 us = xw2[(size_t)node * 32 + lane];
    float2 ps = __half22float2(*reinterpret_cast<__half2*>(&us.x));
    float2 qs = __half22float2(*reinterpret_cast<__half2*>(&us.y));
    float4 bb = reinterpret_cast<const float4*>(b)[lane];

    float4 r;
    r.x = fmaxf(dd * (acc0.x + acc1.x + dd * ps.x) + bb.x, 0.f);
    r.y = fmaxf(dd * (acc0.y + acc1.y + dd * ps.y) + bb.y, 0.f);
    r.z = fmaxf(dd * (acc0.z + acc1.z + dd * qs.x) + bb.z, 0.f);
    r.w = fmaxf(dd * (acc0.w + acc1.w + dd * qs.y) + bb.w, 0.f);
    reinterpret_cast<float4*>(out)[(size_t)node * 32 + lane] = r;
}

// ---------------------------------------------------------------------------
// Launch
// ---------------------------------------------------------------------------
extern "C" void kernel_launch(void* const* d_in, const int* in_sizes, int n_in,
                              void* d_out, int out_size)
{
    const float* x  = (const float*)d_in[0];
    const int*   ei = (const int*)d_in[1];
    const float* W1 = (const float*)d_in[2];
    const float* b1 = (const float*)d_in[3];
    const float* W2 = (const float*)d_in[4];
    const float* b2 = (const float*)d_in[5];
    float* out = (float*)d_out;

    const int n = in_sizes[0] / H;       // 50000
    const int e = in_sizes[1] / 2;       // 600000

    float*  dinv;   cudaGetSymbolAddress((void**)&dinv,   g_dinv);
    int*    cnt;    cudaGetSymbolAddress((void**)&cnt,    g_cnt);
    int*    off;    cudaGetSymbolAddress((void**)&off,    g_off);
    int*    cursor; cudaGetSymbolAddress((void**)&cursor, g_cursor);
    int*    csr;    cudaGetSymbolAddress((void**)&csr,    g_csr_src);
    __half* xw;     cudaGetSymbolAddress((void**)&xw,     g_xw);
    float*  h;      cudaGetSymbolAddress((void**)&h,      g_h);

    const int smem_w = 128 * WPAD * sizeof(float);   // 69,632 B
    static int smem_set = 0;
    if (!smem_set) {
        cudaFuncSetAttribute(gemm_tf32_kernel,
                             cudaFuncAttributeMaxDynamicSharedMemorySize, smem_w);
        smem_set = 1;
    }

    const int T = 256;
    const int blocks_n    = (n + T - 1) / T;
    const int blocks_e    = (e + T - 1) / T;
    const int blocks_gemm = (n + 127) / 128;
    const int blocks_gath = (n * 32 + T - 1) / T;

    // CSR build (shared by both layers)
    zero_cnt_kernel<<<blocks_n, T>>>(cnt, n);
    count_kernel<<<blocks_e, T>>>(ei, cnt, e);
    scan_kernel<<<1, SCAN_T>>>(cnt, off, cursor, dinv, n);
    fill_kernel<<<blocks_e, T>>>(ei, cursor, csr, e);

    // layer 1
    gemm_tf32_kernel<<<blocks_gemm, T, smem_w>>>(x, W1, xw, n);
    gather_kernel<<<blocks_gath, T>>>(csr, off, dinv, xw, b1, h, n);

    // layer 2
    gemm_tf32_kernel<<<blocks_gemm, T, smem_w>>>(h, W2, xw, n);
    gather_kernel<<<blocks_gath, T>>>(csr, off, dinv, xw, b2, out, n);
}